// round 10
// baseline (speedup 1.0000x reference)
#include <cuda_runtime.h>
#include <cuda_bf16.h>

// Problem constants
#define NB 16
#define NC 256
#define HW 4096
#define ENH_ELEMS (NB * NC * HW)       // 16777216
#define ENT_ELEMS (NB * HW)            // 65536 per map
#define GRID 592                       // 4 blocks/SM x 148 SMs, all co-resident
#define NWARPS (GRID * 8)              // 4736
#define OUT_BLOCKS (ENH_ELEMS / 4 / 256)   // 16384
#define ENT_BLOCKS (2 * ENT_ELEMS / 256)   // 512
#define SE_UNITS_TOTAL 4096            // 2 groups x 2048 warp-units

// ---------------- scratch (device globals; no allocation) ----------------
__device__ float g_pooled[2][NB][NC];
__device__ float g_cw[2][NB][NC];
__device__ float g_se[2][NB][HW];
__device__ float g_psum[2][NB][128];   // per 32-px warp unit
__device__ float g_psq[2][NB][128];
__device__ float g_thr[2][NB];
__device__ float g_inv[2][NB];
__device__ unsigned g_ticket;
__device__ unsigned g_bar_cnt;         // auto-resets each barrier
__device__ volatile unsigned g_bar_gen; // monotonic across launches/replays

// ---------------- entropy: log(p+eps) - (1-p)*log(1-p+eps), p=sigmoid(x) ---
// softplus form: log p = -softplus(-x), log(1-p) = -softplus(x)
__device__ __forceinline__ float entropy_val(float x) {
    float a = fabsf(x);
    float t = __expf(-a);                  // e^{-|x|} in (0,1]
    float l = __logf(1.0f + t);            // log(1+e^{-|x|})
    float inv = __fdividef(1.0f, 1.0f + t);
    bool pos = (x >= 0.0f);
    float p      = pos ? inv        : t * inv;   // sigmoid(x)
    float logp   = pos ? -l         : (x - l);   // log p
    float log1mp = pos ? (-x - l)   : -l;        // log (1-p)
    return logp - (1.0f - p) * log1mp;
}

// ---------------- software grid barrier (all GRID blocks co-resident) ------
__device__ __forceinline__ void grid_bar() {
    __syncthreads();
    if (threadIdx.x == 0) {
        __threadfence();
        unsigned gen = g_bar_gen;              // read BEFORE arrive
        unsigned t = atomicAdd(&g_bar_cnt, 1u);
        if (t == GRID - 1) {
            atomicExch(&g_bar_cnt, 0u);
            __threadfence();
            atomicAdd((unsigned*)&g_bar_gen, 1u);
        } else {
            while (g_bar_gen == gen) __nanosleep(64);
        }
        __threadfence();
    }
    __syncthreads();
}

// ---------------- pool warp-unit: one channel row (4096 floats) ------------
__device__ __forceinline__ void pool_unit(const float* __restrict__ vis,
                                          const float* __restrict__ text,
                                          int g, int r, int lane) {
    int f = r >> 11;                    // 2048 rows per feat per group
    int b = g * 8 + ((r >> 8) & 7);
    int c = r & 255;
    const float4* row = (const float4*)((f ? text : vis) + ((size_t)(b * NC + c) << 12));
    float acc = 0.0f;
    #pragma unroll 8
    for (int k = 0; k < 32; k++) {
        float4 v = row[k * 32 + lane];
        acc += (v.x + v.y) + (v.z + v.w);
    }
    #pragma unroll
    for (int o = 16; o; o >>= 1) acc += __shfl_xor_sync(0xffffffffu, acc, o);
    if (lane == 0) g_pooled[f][b][c] = acc * (1.0f / HW);
}

// ---------------- se warp-unit: 32 pixels x 256 channels -------------------
__device__ __forceinline__ void se_unit(const float* __restrict__ vis,
                                        const float* __restrict__ text,
                                        int g, int v, int lane) {
    int fbd = 15 - (v >> 7);            // descending slabs within group
    int f = fbd >> 3;
    int b = g * 8 + (fbd & 7);
    int ws = v & 127;                   // 128 units of 32 px per (f,b)
    int px = ws * 32 + lane;
    const float* feat = (f ? text : vis) + ((size_t)(b * NC) << 12) + px;
    const float* cwp = g_cw[f][b];

    float acc = 0.0f;
    #pragma unroll 8
    for (int c = 0; c < NC; c++) {
        float x = __ldg(feat + ((size_t)c << 12));
        acc = fmaf(entropy_val(x), __ldg(cwp + c), acc);
    }
    g_se[f][b][px] = acc;

    float s = acc, q = acc * acc;
    #pragma unroll
    for (int o = 16; o; o >>= 1) {
        s += __shfl_xor_sync(0xffffffffu, s, o);
        q += __shfl_xor_sync(0xffffffffu, q, o);
    }
    unsigned t = 0;
    if (lane == 0) {
        g_psum[f][b][ws] = s;
        g_psq [f][b][ws] = q;
        __threadfence();                // publish partials before arrive
        t = atomicAdd(&g_ticket, 1u);
    }
    t = __shfl_sync(0xffffffffu, t, 0);
    if (t == SE_UNITS_TOTAL - 1) {      // last se unit globally: final stats
        __threadfence();
        int ff = lane >> 4, bb = lane & 15;
        float S = 0.0f, Q = 0.0f;
        #pragma unroll 4
        for (int i = 0; i < 128; i++) { S += g_psum[ff][bb][i]; Q += g_psq[ff][bb][i]; }
        g_thr[ff][bb] = S * (0.5f / HW);            // mean(se)*0.5 (scale-free)
        g_inv[ff][bb] = 1.0f / fmaxf(sqrtf(Q), 1e-12f);
    }
}

// ---------------- mlp for one (f,b): blocks 0..15 of a group ----------------
__device__ __forceinline__ void mlp_block(int g, int bid, int tid,
                                          float* sp, float* sh,
                                          const float* __restrict__ w1,
                                          const float* __restrict__ b1,
                                          const float* __restrict__ w2,
                                          const float* __restrict__ b2) {
    int f = bid >> 3, b = g * 8 + (bid & 7);
    sp[tid] = g_pooled[f][b][tid];
    __syncthreads();
    if (tid < 64) {
        float acc = b1[tid];
        #pragma unroll 8
        for (int i = 0; i < NC; i++) acc = fmaf(sp[i], w1[i * 64 + tid], acc);
        sh[tid] = fmaxf(acc, 0.0f);
    }
    __syncthreads();
    float acc = b2[tid];
    #pragma unroll 8
    for (int j = 0; j < 64; j++) acc = fmaf(sh[j], w2[j * NC + tid], acc);
    g_cw[f][b][tid] = __fdividef(1.0f, 1.0f + __expf(-acc));
}

// ---------------- fused persistent kernel: pool -> mlp -> se, 2 groups -----
// Group working set (8 batches x 2 feats = 67 MB) stays L2-resident between
// its pool phase and its se phase; poolG2's DRAM stream overlaps seG1.
__global__ void __launch_bounds__(256, 4)
k_fused(const float* __restrict__ vis, const float* __restrict__ text,
        const float* __restrict__ w1, const float* __restrict__ b1,
        const float* __restrict__ w2, const float* __restrict__ b2) {
    __shared__ float sp[NC];
    __shared__ float sh[64];
    int tid = threadIdx.x, bid = blockIdx.x;
    int lane = tid & 31;
    int wg = bid * 8 + (tid >> 5);      // global warp id, 0..4735

    if (bid == 0 && tid == 0) g_ticket = 0;

    // phase A: pool group 0 (4096 warp-rows)
    for (int u = wg; u < 4096; u += NWARPS) pool_unit(vis, text, 0, u, lane);
    grid_bar();
    if (bid < 16) mlp_block(0, bid, tid, sp, sh, w1, b1, w2, b2);
    grid_bar();
    // phase C: se group 0 (2048 units) then pool group 1 (4096 rows), overlapped
    for (int u = wg; u < 6144; u += NWARPS) {
        if (u < 2048) se_unit(vis, text, 0, u, lane);
        else          pool_unit(vis, text, 1, u - 2048, lane);
    }
    grid_bar();
    if (bid < 16) mlp_block(1, bid, tid, sp, sh, w1, b1, w2, b2);
    grid_bar();
    // phase E: se group 1 (2048 units); last unit computes thr/inv
    for (int u = wg; u < 2048; u += NWARPS) se_unit(vis, text, 1, u, lane);
}

// ---------------- K2: blend (ASC, hits G2's L2-resident 67 MB) + ent tail ---
__global__ void k_out(const float* __restrict__ vis, const float* __restrict__ text,
                      float* __restrict__ out) {
    if (blockIdx.x >= OUT_BLOCKS) {
        int idx = (blockIdx.x - OUT_BLOCKS) * 256 + threadIdx.x;   // 0..131071
        int f   = idx >> 16;
        int rem = idx & 65535;
        int b   = rem >> 12;
        int pix = rem & 4095;
        __stcs(out + ENH_ELEMS + idx, g_se[f][b][pix] * g_inv[f][b]);
        return;
    }
    int idx4 = blockIdx.x * 256 + threadIdx.x;      // 0 .. 4194303
    int pix4 = idx4 & 1023;                         // HW/4 = 1024
    int b    = idx4 >> 18;                          // / (NC*1024)
    float thr_v = g_thr[0][b];
    float thr_t = g_thr[1][b];
    float4 sev = ((const float4*)g_se[0][b])[pix4];
    float4 set = ((const float4*)g_se[1][b])[pix4];
    float4 v = __ldcs(((const float4*)vis) + idx4);   // last use: evict-first
    float4 t = __ldcs(((const float4*)text) + idx4);
    float4 o;
    o.x = (sev.x < thr_v) ? v.x : ((set.x < thr_t) ? t.x : 0.0f);
    o.y = (sev.y < thr_v) ? v.y : ((set.y < thr_t) ? t.y : 0.0f);
    o.z = (sev.z < thr_v) ? v.z : ((set.z < thr_t) ? t.z : 0.0f);
    o.w = (sev.w < thr_v) ? v.w : ((set.w < thr_t) ? t.w : 0.0f);
    __stcs(((float4*)out) + idx4, o);                 // write-once: stream
}

// ---------------- launch ----------------
extern "C" void kernel_launch(void* const* d_in, const int* in_sizes, int n_in,
                              void* d_out, int out_size) {
    const float* vis  = (const float*)d_in[0];
    const float* text = (const float*)d_in[1];
    const float* w1   = (const float*)d_in[2];
    const float* b1   = (const float*)d_in[3];
    const float* w2   = (const float*)d_in[4];
    const float* b2   = (const float*)d_in[5];
    float* out = (float*)d_out;

    k_fused<<<GRID, 256>>>(vis, text, w1, b1, w2, b2);
    k_out  <<<OUT_BLOCKS + ENT_BLOCKS, 256>>>(vis, text, out);
}

// round 11
// speedup vs baseline: 1.3655x; 1.3655x over previous
#include <cuda_runtime.h>
#include <cuda_bf16.h>

// Problem constants
#define NB 16
#define NC 256
#define HW 4096
#define ENH_ELEMS (NB * NC * HW)       // 16777216
#define GRID 592                       // 4 blocks/SM x 148 SMs, all co-resident
#define NWARPS (GRID * 8)              // 4736
#define POOL_UNITS 8192                // one 16KB channel row each
#define SE_UNITS 8192                  // 16 px x 256 ch each
#define OUT_UNITS 8224                 // 8192 half-rows + 32 ent maps

// ---------------- scratch (device globals; no allocation) ----------------
__device__ float g_pooled[2][NB][NC];
__device__ float g_cw[2][NB][NC];
__device__ float g_se[2][NB][HW];
__device__ float g_psum[2][NB][256];   // per 16-px unit
__device__ float g_psq[2][NB][256];
__device__ float g_thr[2][NB];
__device__ float g_inv[2][NB];
__device__ unsigned g_tick[3];          // pool, se, out (reset at kernel end)
__device__ unsigned g_bar_cnt;          // self-resetting
__device__ volatile unsigned g_bar_gen; // monotonic across launches/replays

// ---------------- entropy: log(p+eps) - (1-p)*log(1-p+eps), p=sigmoid(x) ---
__device__ __forceinline__ float entropy_val(float x) {
    float a = fabsf(x);
    float t = __expf(-a);                  // e^{-|x|}
    float l = __logf(1.0f + t);
    float inv = __fdividef(1.0f, 1.0f + t);
    bool pos = (x >= 0.0f);
    float p      = pos ? inv        : t * inv;   // sigmoid(x)
    float logp   = pos ? -l         : (x - l);   // log p
    float log1mp = pos ? (-x - l)   : -l;        // log (1-p)
    return logp - (1.0f - p) * log1mp;
}

// ---------------- software grid barrier (R9-proven) ------------------------
__device__ __forceinline__ void grid_bar() {
    __syncthreads();
    if (threadIdx.x == 0) {
        __threadfence();
        unsigned gen = g_bar_gen;              // read BEFORE arrive
        unsigned t = atomicAdd(&g_bar_cnt, 1u);
        if (t == GRID - 1) {
            atomicExch(&g_bar_cnt, 0u);
            __threadfence();
            atomicAdd((unsigned*)&g_bar_gen, 1u);
        } else {
            while (g_bar_gen == gen) __nanosleep(64);
        }
        __threadfence();
    }
    __syncthreads();
}

// ---------------- pool unit: one channel row (ascending addresses) ---------
__device__ __forceinline__ void pool_unit(const float* __restrict__ vis,
                                          const float* __restrict__ text,
                                          int u, int lane) {
    int f  = u >> 12;
    int bc = u & 4095;
    const float4* row = (const float4*)((f ? text : vis) + ((size_t)bc << 12));
    float acc = 0.0f;
    #pragma unroll 8
    for (int k = 0; k < 32; k++) {
        float4 v = row[k * 32 + lane];
        acc += (v.x + v.y) + (v.z + v.w);
    }
    #pragma unroll
    for (int o = 16; o; o >>= 1) acc += __shfl_xor_sync(0xffffffffu, acc, o);
    if (lane == 0) g_pooled[f][bc >> 8][bc & 255] = acc * (1.0f / HW);
}

// ---------------- se unit: 16 px x 256 ch, descending slabs ----------------
__device__ __forceinline__ void se_unit(const float* __restrict__ vis,
                                        const float* __restrict__ text,
                                        int u, int lane) {
    int slab = 31 - (u >> 8);              // early tickets -> high addresses
    int f = slab >> 4, b = slab & 15;
    int unit = u & 255;
    int px = unit * 16 + (lane >> 1);      // 2 lanes per pixel
    int cb = (lane & 1) << 7;              // channel half: 0 / 128
    const float* feat = (f ? text : vis) + ((size_t)(b * NC + cb) << 12) + px;
    const float* cwp  = g_cw[f][b] + cb;

    float acc = 0.0f;
    #pragma unroll 8
    for (int c = 0; c < 128; c++) {
        float x = __ldg(feat + ((size_t)c << 12));
        acc = fmaf(entropy_val(x), __ldg(cwp + c), acc);
    }
    acc += __shfl_xor_sync(0xffffffffu, acc, 1);   // combine channel halves
    if ((lane & 1) == 0) g_se[f][b][px] = acc;

    float s = (lane & 1) ? 0.0f : acc;             // count each pixel once
    float q = (lane & 1) ? 0.0f : acc * acc;
    #pragma unroll
    for (int o = 16; o; o >>= 1) {
        s += __shfl_xor_sync(0xffffffffu, s, o);
        q += __shfl_xor_sync(0xffffffffu, q, o);
    }
    if (lane == 0) { g_psum[f][b][unit] = s; g_psq[f][b][unit] = q; }
}

// ---------------- out unit: half-row blend / ent map (ascending) -----------
__device__ __forceinline__ void out_unit(const float* __restrict__ vis,
                                         const float* __restrict__ text,
                                         float* __restrict__ out,
                                         int u, int lane) {
    if (u < 8192) {
        size_t base4 = (size_t)u << 9;             // float4 index, 512 per unit
        int b  = (int)(base4 >> 18);
        int p0 = (int)(base4 & 1023);              // 0 or 512 within the row
        float thr_v = g_thr[0][b];
        float thr_t = g_thr[1][b];
        const float4* sev4 = (const float4*)g_se[0][b] + p0;
        const float4* set4 = (const float4*)g_se[1][b] + p0;
        const float4* v4 = (const float4*)vis + base4;
        const float4* t4 = (const float4*)text + base4;
        float4* o4 = (float4*)out + base4;
        #pragma unroll 4
        for (int i = lane; i < 512; i += 32) {
            float4 sev = sev4[i];
            float4 set = set4[i];
            float4 v = __ldcs(v4 + i);
            float4 t = __ldcs(t4 + i);
            float4 o;
            o.x = (sev.x < thr_v) ? v.x : ((set.x < thr_t) ? t.x : 0.0f);
            o.y = (sev.y < thr_v) ? v.y : ((set.y < thr_t) ? t.y : 0.0f);
            o.z = (sev.z < thr_v) ? v.z : ((set.z < thr_t) ? t.z : 0.0f);
            o.w = (sev.w < thr_v) ? v.w : ((set.w < thr_t) ? t.w : 0.0f);
            __stcs(o4 + i, o);
        }
    } else {
        int u2 = u - 8192;                         // 0..31: one entropy map
        int f = u2 >> 4, b = u2 & 15;
        float inv = g_inv[f][b];
        const float4* s4 = (const float4*)g_se[f][b];
        float4* d4 = (float4*)(out + ENH_ELEMS + u2 * HW);
        #pragma unroll 4
        for (int i = lane; i < 1024; i += 32) {
            float4 s = s4[i];
            float4 o; o.x = s.x * inv; o.y = s.y * inv; o.z = s.z * inv; o.w = s.w * inv;
            __stcs(d4 + i, o);
        }
    }
}

// ---------------- mlp for one (f,b): blocks 0..31 --------------------------
__device__ __forceinline__ void mlp_block(int bid, int tid, float* sp, float* sh,
                                          const float* __restrict__ w1,
                                          const float* __restrict__ b1,
                                          const float* __restrict__ w2,
                                          const float* __restrict__ b2) {
    int f = bid >> 4, b = bid & 15;
    sp[tid] = g_pooled[f][b][tid];
    __syncthreads();
    if (tid < 64) {
        float acc = b1[tid];
        #pragma unroll 8
        for (int i = 0; i < NC; i++) acc = fmaf(sp[i], w1[i * 64 + tid], acc);
        sh[tid] = fmaxf(acc, 0.0f);
    }
    __syncthreads();
    float acc = b2[tid];
    #pragma unroll 8
    for (int j = 0; j < 64; j++) acc = fmaf(sh[j], w2[j * NC + tid], acc);
    g_cw[f][b][tid] = __fdividef(1.0f, 1.0f + __expf(-acc));
}

// ---------------- the whole pipeline in one persistent kernel --------------
__global__ void __launch_bounds__(256, 4)
k_fused(const float* __restrict__ vis, const float* __restrict__ text,
        const float* __restrict__ w1, const float* __restrict__ b1,
        const float* __restrict__ w2, const float* __restrict__ b2,
        float* __restrict__ out) {
    __shared__ float sp[NC];
    __shared__ float sh[64];
    int tid = threadIdx.x, bid = blockIdx.x;
    int lane = tid & 31;
    int wg = bid * 8 + (tid >> 5);      // 0..4735

    // ---- phase 1: pool (ticket-scheduled; first unit static) ----
    pool_unit(vis, text, wg, lane);
    for (;;) {
        unsigned u = 0;
        if (lane == 0) u = NWARPS + atomicAdd(&g_tick[0], 1u);
        u = __shfl_sync(0xffffffffu, u, 0);
        if (u >= POOL_UNITS) break;
        pool_unit(vis, text, (int)u, lane);
    }
    grid_bar();

    // ---- phase 2: mlp ----
    if (bid < 32) mlp_block(bid, tid, sp, sh, w1, b1, w2, b2);
    grid_bar();

    // ---- phase 3: se (descending slabs, ticket-scheduled) ----
    se_unit(vis, text, wg, lane);
    for (;;) {
        unsigned u = 0;
        if (lane == 0) u = NWARPS + atomicAdd(&g_tick[1], 1u);
        u = __shfl_sync(0xffffffffu, u, 0);
        if (u >= SE_UNITS) break;
        se_unit(vis, text, (int)u, lane);
    }
    grid_bar();

    // ---- phase 4: stats (block 0, 256 threads = 32 fb x 8 lanes) ----
    if (bid == 0) {
        int fb = tid >> 3, j = tid & 7;
        int f = fb >> 4, b = fb & 15;
        float S = 0.0f, Q = 0.0f;
        #pragma unroll 8
        for (int k = 0; k < 32; k++) {
            int i = j * 32 + k;
            S += g_psum[f][b][i];
            Q += g_psq[f][b][i];
        }
        #pragma unroll
        for (int o = 4; o; o >>= 1) {              // reduce over j (lanes 1,2,4 apart)
            S += __shfl_xor_sync(0xffffffffu, S, o);
            Q += __shfl_xor_sync(0xffffffffu, Q, o);
        }
        if (j == 0) {
            g_thr[f][b] = S * (0.5f / HW);         // mean(se)*0.5 (scale-free vs normalize)
            g_inv[f][b] = 1.0f / fmaxf(sqrtf(Q), 1e-12f);
        }
    }
    grid_bar();

    // ---- phase 5: out blend + ent maps (ascending, hits se's hot L2) ----
    out_unit(vis, text, out, wg, lane);
    for (;;) {
        unsigned u = 0;
        if (lane == 0) u = NWARPS + atomicAdd(&g_tick[2], 1u);
        u = __shfl_sync(0xffffffffu, u, 0);
        if (u >= OUT_UNITS) break;
        out_unit(vis, text, out, (int)u, lane);
    }

    // ---- epilogue: reset tickets for the next graph replay ----
    grid_bar();
    if (bid == 0 && tid == 0) {
        g_tick[0] = 0; g_tick[1] = 0; g_tick[2] = 0;
    }
}

// ---------------- launch ----------------
extern "C" void kernel_launch(void* const* d_in, const int* in_sizes, int n_in,
                              void* d_out, int out_size) {
    const float* vis  = (const float*)d_in[0];
    const float* text = (const float*)d_in[1];
    const float* w1   = (const float*)d_in[2];
    const float* b1   = (const float*)d_in[3];
    const float* w2   = (const float*)d_in[4];
    const float* b2   = (const float*)d_in[5];
    float* out = (float*)d_out;

    k_fused<<<GRID, 256>>>(vis, text, w1, b1, w2, b2, out);
}

// round 15
// speedup vs baseline: 1.3926x; 1.0198x over previous
#include <cuda_runtime.h>
#include <cuda_bf16.h>

// Problem constants
#define NB 16
#define NC 256
#define HW 4096
#define ENH_ELEMS (NB * NC * HW)       // 16777216
#define ENT_ELEMS (NB * HW)            // 65536 per map
#define GRID 592                       // 4 blocks/SM x 148 SMs, co-resident
#define NWARPS (GRID * 8)              // 4736
#define PUNITS 8192u                   // pool: one 16KB channel row per unit
#define SUNITS 8192u                   // se: 16 px x 256 ch per unit
#define UMASK  8191u
#define OUT_BLOCKS (ENH_ELEMS / 4 / 256)   // 16384
#define ENT_BLOCKS (2 * ENT_ELEMS / 256)   // 512

// ---------------- scratch (device globals; no allocation) ----------------
__device__ float g_pooled[2][NB][NC];
__device__ float g_cw[2][NB][NC];
__device__ float g_se[2][NB][HW];
__device__ float g_psum[2][NB][256];   // per 16-px unit
__device__ float g_psq[2][NB][256];
__device__ float g_thr[2][NB];
__device__ float g_inv[2][NB];
// reset-free counters: advance by exactly UNITS per replay (deterministic),
// UNITS is a power of two, so (raw & UMASK) is the within-replay index.
__device__ unsigned g_tick_pool, g_tick_se, g_done;
__device__ unsigned g_bar_cnt;          // self-resetting
__device__ volatile unsigned g_bar_gen; // monotonic across launches/replays

// ---------------- entropy: log(p+eps) - (1-p)*log(1-p+eps), p=sigmoid(x) ---
__device__ __forceinline__ float entropy_val(float x) {
    float a = fabsf(x);
    float t = __expf(-a);                  // e^{-|x|}
    float l = __logf(1.0f + t);
    float inv = __fdividef(1.0f, 1.0f + t);
    bool pos = (x >= 0.0f);
    float p      = pos ? inv        : t * inv;   // sigmoid(x)
    float logp   = pos ? -l         : (x - l);   // log p
    float log1mp = pos ? (-x - l)   : -l;        // log (1-p)
    return logp - (1.0f - p) * log1mp;
}

// ---------------- software grid barrier (R9/R10-proven) --------------------
__device__ __forceinline__ void grid_bar() {
    __syncthreads();
    if (threadIdx.x == 0) {
        __threadfence();
        unsigned gen = g_bar_gen;              // read BEFORE arrive
        unsigned t = atomicAdd(&g_bar_cnt, 1u);
        if (t == GRID - 1) {
            atomicExch(&g_bar_cnt, 0u);
            __threadfence();
            atomicAdd((unsigned*)&g_bar_gen, 1u);
        } else {
            while (g_bar_gen == gen) __nanosleep(64);
        }
        __threadfence();
    }
    __syncthreads();
}

// ---------------- pool unit: one channel row (ascending addresses) ---------
__device__ __forceinline__ void pool_unit(const float* __restrict__ vis,
                                          const float* __restrict__ text,
                                          int u, int lane) {
    int f  = u >> 12;
    int bc = u & 4095;
    const float4* row = (const float4*)((f ? text : vis) + ((size_t)bc << 12));
    float acc = 0.0f;
    #pragma unroll 8
    for (int k = 0; k < 32; k++) {
        float4 v = row[k * 32 + lane];
        acc += (v.x + v.y) + (v.z + v.w);
    }
    #pragma unroll
    for (int o = 16; o; o >>= 1) acc += __shfl_xor_sync(0xffffffffu, acc, o);
    if (lane == 0) g_pooled[f][bc >> 8][bc & 255] = acc * (1.0f / HW);
}

// ---------------- se unit: 16 px x 256 ch, descending slabs ----------------
// Descending so the first units read pool's L2-resident tail (same kernel).
// The warp observing the LAST completion also computes thr/inv (stats).
__device__ __forceinline__ void se_unit(const float* __restrict__ vis,
                                        const float* __restrict__ text,
                                        int u, int lane) {
    int slab = 31 - (u >> 8);              // early units -> high addresses
    int f = slab >> 4, b = slab & 15;
    int unit = u & 255;
    int px = unit * 16 + (lane >> 1);      // 2 lanes per pixel
    int cb = (lane & 1) << 7;              // channel half: 0 / 128
    const float* feat = (f ? text : vis) + ((size_t)(b * NC + cb) << 12) + px;
    const float* cwp  = g_cw[f][b] + cb;

    float acc = 0.0f;
    #pragma unroll 8
    for (int c = 0; c < 128; c++) {
        float x = __ldg(feat + ((size_t)c << 12));
        acc = fmaf(entropy_val(x), __ldg(cwp + c), acc);
    }
    acc += __shfl_xor_sync(0xffffffffu, acc, 1);   // combine channel halves
    if ((lane & 1) == 0) g_se[f][b][px] = acc;

    float s = (lane & 1) ? 0.0f : acc;             // count each pixel once
    float q = (lane & 1) ? 0.0f : acc * acc;
    #pragma unroll
    for (int o = 16; o; o >>= 1) {
        s += __shfl_xor_sync(0xffffffffu, s, o);
        q += __shfl_xor_sync(0xffffffffu, q, o);
    }
    unsigned d = 0;
    if (lane == 0) {
        g_psum[f][b][unit] = s;
        g_psq [f][b][unit] = q;
        __threadfence();                           // publish before arrive
        d = atomicAdd(&g_done, 1u);
    }
    d = __shfl_sync(0xffffffffu, d, 0);
    if ((d & UMASK) == SUNITS - 1) {               // last se unit this replay
        __threadfence();                           // acquire all partials
        int ff = lane >> 4, bb = lane & 15;        // 32 lanes -> 32 (f,b)
        float S = 0.0f, Q = 0.0f;
        #pragma unroll 8
        for (int i = 0; i < 256; i++) { S += g_psum[ff][bb][i]; Q += g_psq[ff][bb][i]; }
        g_thr[ff][bb] = S * (0.5f / HW);           // mean(se)*0.5 (scale-free)
        g_inv[ff][bb] = 1.0f / fmaxf(sqrtf(Q), 1e-12f);
    }
}

// ---------------- mlp for one (f,b): blocks 0..31 --------------------------
__device__ __forceinline__ void mlp_block(int bid, int tid, float* sp, float* sh,
                                          const float* __restrict__ w1,
                                          const float* __restrict__ b1,
                                          const float* __restrict__ w2,
                                          const float* __restrict__ b2) {
    int f = bid >> 4, b = bid & 15;
    sp[tid] = g_pooled[f][b][tid];
    __syncthreads();
    if (tid < 64) {
        float acc = b1[tid];
        #pragma unroll 8
        for (int i = 0; i < NC; i++) acc = fmaf(sp[i], w1[i * 64 + tid], acc);
        sh[tid] = fmaxf(acc, 0.0f);
    }
    __syncthreads();
    float acc = b2[tid];
    #pragma unroll 8
    for (int j = 0; j < 64; j++) acc = fmaf(sh[j], w2[j * NC + tid], acc);
    g_cw[f][b][tid] = __fdividef(1.0f, 1.0f + __expf(-acc));
}

// ---------------- fused persistent: pool -> mlp -> se(+stats) --------------
__global__ void __launch_bounds__(256, 4)
k_fused(const float* __restrict__ vis, const float* __restrict__ text,
        const float* __restrict__ w1, const float* __restrict__ b1,
        const float* __restrict__ w2, const float* __restrict__ b2) {
    __shared__ float sp[NC];
    __shared__ float sh[64];
    int tid = threadIdx.x, bid = blockIdx.x;
    int lane = tid & 31;
    int wg = bid * 8 + (tid >> 5);      // 0..4735

    // ---- phase 1: pool (static first unit + reset-free tickets) ----
    pool_unit(vis, text, wg, lane);
    for (;;) {
        unsigned raw = 0;
        if (lane == 0) raw = atomicAdd(&g_tick_pool, 1u);
        raw = __shfl_sync(0xffffffffu, raw, 0);
        unsigned rel = raw & UMASK;
        if (rel >= PUNITS - NWARPS) break;         // stop token
        pool_unit(vis, text, (int)(NWARPS + rel), lane);
    }
    grid_bar();

    // ---- phase 2: mlp (32 blocks) ----
    if (bid < 32) mlp_block(bid, tid, sp, sh, w1, b1, w2, b2);
    grid_bar();

    // ---- phase 3: se (descending; reads pool's L2-resident data) ----
    se_unit(vis, text, wg, lane);
    for (;;) {
        unsigned raw = 0;
        if (lane == 0) raw = atomicAdd(&g_tick_se, 1u);
        raw = __shfl_sync(0xffffffffu, raw, 0);
        unsigned rel = raw & UMASK;
        if (rel >= SUNITS - NWARPS) break;         // stop token
        se_unit(vis, text, (int)(NWARPS + rel), lane);
    }
    // no epilogue barrier needed: counters are reset-free (mod power-of-2)
}

// ---------------- K2: blend (ASC, hits se's low-address L2 tail) + ent -----
__global__ void k_out(const float* __restrict__ vis, const float* __restrict__ text,
                      float* __restrict__ out) {
    if (blockIdx.x >= OUT_BLOCKS) {
        int idx = (blockIdx.x - OUT_BLOCKS) * 256 + threadIdx.x;   // 0..131071
        int f   = idx >> 16;
        int rem = idx & 65535;
        int b   = rem >> 12;
        int pix = rem & 4095;
        __stcs(out + ENH_ELEMS + idx, g_se[f][b][pix] * g_inv[f][b]);
        return;
    }
    int idx4 = blockIdx.x * 256 + threadIdx.x;      // 0 .. 4194303
    int pix4 = idx4 & 1023;                         // HW/4 = 1024
    int b    = idx4 >> 18;                          // / (NC*1024)
    float thr_v = g_thr[0][b];
    float thr_t = g_thr[1][b];
    float4 sev = ((const float4*)g_se[0][b])[pix4];
    float4 set = ((const float4*)g_se[1][b])[pix4];
    float4 v = __ldcs(((const float4*)vis) + idx4);   // last use: evict-first
    float4 t = __ldcs(((const float4*)text) + idx4);
    float4 o;
    o.x = (sev.x < thr_v) ? v.x : ((set.x < thr_t) ? t.x : 0.0f);
    o.y = (sev.y < thr_v) ? v.y : ((set.y < thr_t) ? t.y : 0.0f);
    o.z = (sev.z < thr_v) ? v.z : ((set.z < thr_t) ? t.z : 0.0f);
    o.w = (sev.w < thr_v) ? v.w : ((set.w < thr_t) ? t.w : 0.0f);
    __stcs(((float4*)out) + idx4, o);                 // write-once: stream
}

// ---------------- launch ----------------
extern "C" void kernel_launch(void* const* d_in, const int* in_sizes, int n_in,
                              void* d_out, int out_size) {
    const float* vis  = (const float*)d_in[0];
    const float* text = (const float*)d_in[1];
    const float* w1   = (const float*)d_in[2];
    const float* b1   = (const float*)d_in[3];
    const float* w2   = (const float*)d_in[4];
    const float* b2   = (const float*)d_in[5];
    float* out = (float*)d_out;

    k_fused<<<GRID, 256>>>(vis, text, w1, b1, w2, b2);
    k_out  <<<OUT_BLOCKS + ENT_BLOCKS, 256>>>(vis, text, out);
}